// round 7
// baseline (speedup 1.0000x reference)
#include <cuda_runtime.h>
#include <cuda_bf16.h>

#define FULLMASK 0xffffffffu

// ---------------------------------------------------------------------------
// Analytic reduction (validated R1-R6, rel_err ~1e-5..2e-5):
// Measured observable is Z on wire 10, touched only by its vertex init and
// edge-loop iteration i=1; everything later commutes and drops out.
//   psi0   = U |vE0>|vN0>|0>|0>            (16-dim, iteration-0 gates)
//   W_a    = U (|vE1>|vN1>|a>)             (same U, shared params)
//   answer = sum_{en,s} (+-)_s | sum_a psi0[en*4+a] * W_a[s] |^2
// Index s: E=bit3, Nb=bit2, A1=bit1, A2=bit0.
//
// R7 layout: lane bits = (E, A2)  [E = lane-bit1, A2 = lane-bit0],
// register index r = (Nb<<1)|A1. This makes 3 of 6 CNOTs free register
// renames and cuts shuffle stages 6 -> 5 (16 SHFLs). The 4 controlled init
// gates fold into 2 per-lane-selected 2x2 stages (products precomputed in
// the prologue, off the critical path).
// ---------------------------------------------------------------------------

struct C2 { float x, y; };
__device__ __forceinline__ C2 cmul(C2 a, C2 b){
    return { a.x*b.x - a.y*b.y, a.x*b.y + a.y*b.x };
}
__device__ __forceinline__ C2 cmadd(C2 a, C2 b, C2 acc){ // acc + a*b
    return { fmaf(a.x, b.x, fmaf(-a.y, b.y, acc.x)),
             fmaf(a.x, b.y, fmaf( a.y, b.x, acc.y)) };
}
__device__ __forceinline__ C2 shf2(C2 v, int m){
    C2 r;
    r.x = __shfl_xor_sync(FULLMASK, v.x, m);
    r.y = __shfl_xor_sync(FULLMASK, v.y, m);
    return r;
}

struct M2 { C2 m00, m01, m10, m11; };

__device__ __forceinline__ M2 mmul(const M2& A, const M2& B){
    M2 R;
    R.m00 = cmadd(A.m01, B.m10, cmul(A.m00, B.m00));
    R.m01 = cmadd(A.m01, B.m11, cmul(A.m00, B.m01));
    R.m10 = cmadd(A.m11, B.m10, cmul(A.m10, B.m00));
    R.m11 = cmadd(A.m11, B.m11, cmul(A.m10, B.m01));
    return R;
}
__device__ __forceinline__ M2 msel(bool p, const M2& A, const M2& B){
    M2 R;
    R.m00 = p ? A.m00 : B.m00;  R.m01 = p ? A.m01 : B.m01;
    R.m10 = p ? A.m10 : B.m10;  R.m11 = p ? A.m11 : B.m11;
    return R;
}

__device__ __forceinline__ M2 m_rx(float t){
    float c, s; __sincosf(0.5f*t, &s, &c);
    return { {c,0.f}, {0.f,-s}, {0.f,-s}, {c,0.f} };
}
__device__ __forceinline__ M2 m_ry(float t){
    float c, s; __sincosf(0.5f*t, &s, &c);
    return { {c,0.f}, {-s,0.f}, {s,0.f}, {c,0.f} };
}
__device__ __forceinline__ M2 m_rz(float t){
    float c, s; __sincosf(0.5f*t, &s, &c);
    return { {c,-s}, {0.f,0.f}, {0.f,0.f}, {c,s} };
}
// Closed-form Rx(t2)*Ry(t1)*Rz(t0)  (ref applies Rz, then Ry, then Rx)
__device__ __forceinline__ M2 m_fused(float t0, float t1, float t2){
    float cz, sz, cy, sy, cx, sx;
    __sincosf(0.5f*t0, &sz, &cz);
    __sincosf(0.5f*t1, &sy, &cy);
    __sincosf(0.5f*t2, &sx, &cx);
    float A = cx*cy, B = sx*sy, Cc = cx*sy, D = sx*cy;
    M2 M;
    M.m00 = cmul({cz,-sz}, {A,-B});
    C2 t  = cmul({cz, sz}, {Cc, D});
    M.m01 = { -t.x, -t.y };
    M.m10 = cmul({cz,-sz}, {Cc,-D});
    M.m11 = cmul({cz, sz}, {A, B});
    return M;
}

__device__ __forceinline__ void bfly(C2& a0, C2& a1, const M2& U){
    C2 t0 = cmadd(U.m01, a1, cmul(U.m00, a0));
    C2 t1 = cmadd(U.m11, a1, cmul(U.m10, a0));
    a0 = t0; a1 = t1;
}
// cross-lane butterfly element: this lane's bit of the target qubit = bit
__device__ __forceinline__ C2 capply(const M2& U, int bit, C2 a, C2 ap){
    C2 cs = bit ? U.m11 : U.m00;
    C2 cp = bit ? U.m10 : U.m01;
    return cmadd(cp, ap, cmul(cs, a));
}
__device__ __forceinline__ void cswap(C2& a, C2& b){
    C2 t = a; a = b; b = t;
}

__global__ void __launch_bounds__(32, 1)
QMessagePassing_44272522887312_kernel(
    const float* __restrict__ inp,     // inputs_flat [34]
    const float* __restrict__ inits,   // [4]
    const float* __restrict__ sp0,     // strong0_params [9]
    const float* __restrict__ sp1,     // strong1_params [9]
    float* __restrict__ out)
{
    // sh[t*16 + s]: t=0..3 -> W_t, t=4 -> psi0
    __shared__ C2 sh[80];

    const int tid = threadIdx.x;
    const int sub = tid & 3;
    const int E   = (sub >> 1) & 1;    // lane bit1  (shuffle mask 2)
    const int A2  = sub & 1;           // lane bit0  (shuffle mask 1)
    const int task = (tid < 20) ? (tid >> 2) : 4;

    // ---- parameter loads up front (independent -> MLP)
    const float4 ii  = *(const float4*)inits;
    const float4 e01 = *(const float4*)(inp);        // inp[0..3]
    const float2 n0a = *(const float2*)(inp + 18);   // vert[1] (wire 9)
    const float2 n1a = *(const float2*)(inp + 20);   // vert[2] (wire 10)
    const float4 p0a = *(const float4*)(sp0);
    const float4 p0b = *(const float4*)(sp0 + 4);
    const float  p0c = __ldg(sp0 + 8);
    const float4 p1a = *(const float4*)(sp1);
    const float4 p1b = *(const float4*)(sp1 + 4);
    const float  p1c = __ldg(sp1 + 8);

    // init-gate matrices + folded products (prologue, high ILP)
    const M2 ci0 = m_rx(ii.x);
    const M2 ci1 = m_ry(ii.y);
    const M2 ci2 = m_rz(ii.z);
    const M2 ci3 = m_ry(ii.w);
    const M2 ci1ci0 = mmul(ci1, ci0);
    const M2 ci3ci2 = mmul(ci3, ci2);
    // fused strong-block matrices
    const M2 A0f = m_fused(p0a.x, p0a.y, p0a.z);   // strong0 on E
    const M2 A1f = m_fused(p0a.w, p0b.x, p0b.y);   // strong0 on Nb
    const M2 A2f = m_fused(p0b.z, p0b.w, p0c);     // strong0 on A1
    const M2 B0f = m_fused(p1a.x, p1a.y, p1a.z);   // strong1 on A1
    const M2 B1f = m_fused(p1a.w, p1b.x, p1b.y);   // strong1 on Nb
    const M2 B2f = m_fused(p1b.z, p1b.w, p1c);     // strong1 on A2

    // product vectors: v = Rz(phi) Ry(theta) |0>
    auto mkvec = [](float th, float ph, C2* v){
        float ct, st, cp, sp;
        __sincosf(0.5f*th, &st, &ct);
        __sincosf(0.5f*ph, &sp, &cp);
        v[0] = { ct*cp, -ct*sp };
        v[1] = { st*cp,  st*sp };
    };
    C2 vE0[2], vN0[2], vE1[2], vN1[2];
    mkvec(e01.x, e01.y, vE0);   // edge 0
    mkvec(n0a.x, n0a.y, vN0);   // vert[1]
    mkvec(e01.z, e01.w, vE1);   // edge 1
    mkvec(n1a.x, n1a.y, vN1);   // vert[2] (measured)

    // ---- init: regs r=(Nb<<1)|A1; task t nonzero iff A2==t&1, A1==t>>1
    const int tA1 = (task == 4) ? 0 : (task >> 1);
    const int tA2 = (task == 4) ? 0 : (task & 1);
    C2 a[4];
#pragma unroll
    for (int r = 0; r < 4; r++){
        const int Nb = r >> 1, A1 = r & 1;
        C2 prod = (task == 4) ? cmul(vE0[E], vN0[Nb])
                              : cmul(vE1[E], vN1[Nb]);
        a[r] = (A1 == tA1 && A2 == tA2) ? prod : C2{0.f, 0.f};
    }

    // =================== evolve (U) ===================
    // T1 on A1 (reg bit0): pair (a0,a1) [Nb=0]: (E? ci1 : I);
    //                      pair (a2,a3) [Nb=1]: (E? ci1*ci0 : ci0)
    if (E) bfly(a[0], a[1], ci1);
    { M2 m = msel(E, ci1ci0, ci0); bfly(a[2], a[3], m); }

    // T2 on A2 (lane bit0): regs 0,1 [Nb=0]: (E? ci3 : I);
    //                        regs 2,3 [Nb=1]: (E? ci3*ci2 : ci2)
    {
        C2 p0 = shf2(a[0], 1), p1 = shf2(a[1], 1);
        C2 p2 = shf2(a[2], 1), p3 = shf2(a[3], 1);
        if (E){ a[0] = capply(ci3, A2, a[0], p0);
                a[1] = capply(ci3, A2, a[1], p1); }
        M2 m = msel(E, ci3ci2, ci2);
        a[2] = capply(m, A2, a[2], p2);
        a[3] = capply(m, A2, a[3], p3);
    }

    // strong0: A0f on E (lane bit1) — cross stage
    {
        C2 p0 = shf2(a[0], 2), p1 = shf2(a[1], 2);
        C2 p2 = shf2(a[2], 2), p3 = shf2(a[3], 2);
        a[0] = capply(A0f, E, a[0], p0);
        a[1] = capply(A0f, E, a[1], p1);
        a[2] = capply(A0f, E, a[2], p2);
        a[3] = capply(A0f, E, a[3], p3);
    }
    // A1f on Nb (reg bit1)
    bfly(a[0], a[2], A1f); bfly(a[1], a[3], A1f);
    // A2f on A1 (reg bit0)
    bfly(a[0], a[1], A2f); bfly(a[2], a[3], A2f);
    // cnot(E -> Nb): E=1 lanes flip Nb (reg rename under predicate -> SELs)
    if (E){ cswap(a[0], a[2]); cswap(a[1], a[3]); }
    // cnot(Nb -> A1): Nb=1 regs flip A1: swap a2<->a3 (free rename)
    cswap(a[2], a[3]);
    // cnot(A1 -> E): A1=1 regs (a1, a3) swap across lane E
    a[1] = shf2(a[1], 2);
    a[3] = shf2(a[3], 2);

    // strong1: B0f on A1 (reg bit0)
    bfly(a[0], a[1], B0f); bfly(a[2], a[3], B0f);
    // B1f on Nb (reg bit1)
    bfly(a[0], a[2], B1f); bfly(a[1], a[3], B1f);
    // B2f on A2 (lane bit0) — cross stage
    {
        C2 p0 = shf2(a[0], 1), p1 = shf2(a[1], 1);
        C2 p2 = shf2(a[2], 1), p3 = shf2(a[3], 1);
        a[0] = capply(B2f, A2, a[0], p0);
        a[1] = capply(B2f, A2, a[1], p1);
        a[2] = capply(B2f, A2, a[2], p2);
        a[3] = capply(B2f, A2, a[3], p3);
    }
    // cnot(A1 -> Nb): A1=1 regs flip Nb: swap a1<->a3 (free rename)
    cswap(a[1], a[3]);
    // cnot(Nb -> A2): Nb=1 regs (a2, a3) swap across lane A2
    a[2] = shf2(a[2], 1);
    a[3] = shf2(a[3], 1);
    // cnot(A2 -> A1): A2=1 lanes flip A1 (predicated renames -> SELs)
    if (A2){ cswap(a[0], a[1]); cswap(a[2], a[3]); }
    // ==================================================

    // writeout: s = E*8 + Nb*4 + A1*2 + A2
    if (tid < 20){
#pragma unroll
        for (int r = 0; r < 4; r++){
            const int Nb = r >> 1, A1 = r & 1;
            sh[task*16 + E*8 + Nb*4 + A1*2 + A2] = a[r];
        }
    }
    __syncwarp();

    // ---- combine: 64 terms (en 0..3, s 0..15), 2 per lane
    float val = 0.f;
#pragma unroll
    for (int k = 0; k < 2; k++){
        const int T  = tid + 32*k;
        const int en = T >> 4;
        const int s  = T & 15;
        C2 amp = {0.f, 0.f};
#pragma unroll
        for (int q = 0; q < 4; q++)
            amp = cmadd(sh[64 + en*4 + q], sh[q*16 + s], amp);
        float p = amp.x*amp.x + amp.y*amp.y;
        val += ((s >> 2) & 1) ? -p : p;
    }

#pragma unroll
    for (int off = 16; off > 0; off >>= 1)
        val += __shfl_xor_sync(FULLMASK, val, off);
    if (tid == 0) out[0] = val;
}

extern "C" void kernel_launch(void* const* d_in, const int* in_sizes, int n_in,
                              void* d_out, int out_size)
{
    const float* inputs_flat = (const float*)d_in[0];
    const float* inits       = (const float*)d_in[1];
    const float* strong0     = (const float*)d_in[2];
    const float* strong1     = (const float*)d_in[3];
    // d_in[4] (update_params) provably does not affect the measured value.
    QMessagePassing_44272522887312_kernel<<<1, 32>>>(
        inputs_flat, inits, strong0, strong1, (float*)d_out);
}

// round 8
// speedup vs baseline: 1.0190x; 1.0190x over previous
#include <cuda_runtime.h>
#include <cuda_bf16.h>

#define FULLMASK 0xffffffffu

// ---------------------------------------------------------------------------
// Analytic reduction (validated R1-R7, rel_err ~1.8e-5):
// Measured observable is Z on wire 10, touched only by its vertex init and
// edge-loop iteration i=1; everything later commutes and drops out.
//   psi0   = U |vE0>|vN0>|0>|0>            (16-dim, iteration-0 gates)
//   W_a    = U (|vE1>|vN1>|a>)             (same U, shared params)
//   answer = sum_{en,s} (+-)_s | sum_a psi0[en*4+a] * W_a[s] |^2
// Index s: E=bit3, Nb=bit2, A1=bit1, A2=bit0.
//
// Layout (R7): lane bits = (E, A2); register index r = (Nb<<1)|A1.
// R8: code-size compression for the cold-I$ streaming bottleneck.
// All 10 gate matrices are built by ONE shared m_fused path running
// data-parallel on lanes 0..9 (Rx/Ry/Rz = m_fused with zero angles via a
// zero slot in the shared angle table), then broadcast through smem.
// Controlled-init stages un-merged so no matrix products are needed.
// ---------------------------------------------------------------------------

struct C2 { float x, y; };
__device__ __forceinline__ C2 cmul(C2 a, C2 b){
    return { a.x*b.x - a.y*b.y, a.x*b.y + a.y*b.x };
}
__device__ __forceinline__ C2 cmadd(C2 a, C2 b, C2 acc){ // acc + a*b
    return { fmaf(a.x, b.x, fmaf(-a.y, b.y, acc.x)),
             fmaf(a.x, b.y, fmaf( a.y, b.x, acc.y)) };
}
__device__ __forceinline__ C2 shf2(C2 v, int m){
    C2 r;
    r.x = __shfl_xor_sync(FULLMASK, v.x, m);
    r.y = __shfl_xor_sync(FULLMASK, v.y, m);
    return r;
}

struct M2 { C2 m00, m01, m10, m11; };

// Closed-form Rx(t2)*Ry(t1)*Rz(t0)  (ref applies Rz, then Ry, then Rx).
// Rx(t)=f(0,0,t), Ry(t)=f(0,t,0), Rz(t)=f(t,0,0)  -- verified identities.
__device__ __forceinline__ M2 m_fused(float t0, float t1, float t2){
    float cz, sz, cy, sy, cx, sx;
    __sincosf(0.5f*t0, &sz, &cz);
    __sincosf(0.5f*t1, &sy, &cy);
    __sincosf(0.5f*t2, &sx, &cx);
    float A = cx*cy, B = sx*sy, Cc = cx*sy, D = sx*cy;
    M2 M;
    M.m00 = cmul({cz,-sz}, {A,-B});
    C2 t  = cmul({cz, sz}, {Cc, D});
    M.m01 = { -t.x, -t.y };
    M.m10 = cmul({cz,-sz}, {Cc,-D});
    M.m11 = cmul({cz, sz}, {A, B});
    return M;
}

__device__ __forceinline__ void bfly(C2& a0, C2& a1, const M2& U){
    C2 t0 = cmadd(U.m01, a1, cmul(U.m00, a0));
    C2 t1 = cmadd(U.m11, a1, cmul(U.m10, a0));
    a0 = t0; a1 = t1;
}
// cross-lane butterfly element: this lane's bit of the target qubit = bit
__device__ __forceinline__ C2 capply(const M2& U, int bit, C2 a, C2 ap){
    C2 cs = bit ? U.m11 : U.m00;
    C2 cp = bit ? U.m10 : U.m01;
    return cmadd(cp, ap, cmul(cs, a));
}
__device__ __forceinline__ void cswap(C2& a, C2& b){
    C2 t = a; a = b; b = t;
}

// angle-index triples for the 10 matrices (index 22 = zero slot)
__device__ const signed char g_i0[10] = {22,22, 2,22, 4, 7,10,13,16,19};
__device__ const signed char g_i1[10] = {22, 1,22, 3, 5, 8,11,14,17,20};
__device__ const signed char g_i2[10] = { 0,22,22,22, 6, 9,12,15,18,21};

__global__ void __launch_bounds__(32, 1)
QMessagePassing_44272522887312_kernel(
    const float* __restrict__ inp,     // inputs_flat [34]
    const float* __restrict__ inits,   // [4]
    const float* __restrict__ sp0,     // strong0_params [9]
    const float* __restrict__ sp1,     // strong1_params [9]
    float* __restrict__ out)
{
    // shared: mats floats [0..80), angles [80..103), combine C2 at [104..264)
    __shared__ float shf[264];
    C2* shc = (C2*)(shf + 104);        // shc[t*16+s], t=0..3 W_t, t=4 psi0

    const int tid = threadIdx.x;
    const int sub = tid & 3;
    const int E   = (sub >> 1) & 1;    // lane bit1 (shuffle mask 2)
    const int A2  = sub & 1;           // lane bit0 (shuffle mask 1)
    const int task = (tid < 20) ? (tid >> 2) : 4;

    // ---- cooperative angle load: ang[0..3]=inits, [4..12]=sp0, [13..21]=sp1,
    //      ang[22]=0 (zero-angle slot)
    if (tid < 23){
        float v = 0.f;
        if (tid < 4)        v = __ldg(inits + tid);
        else if (tid < 13)  v = __ldg(sp0 + tid - 4);
        else if (tid < 22)  v = __ldg(sp1 + tid - 13);
        shf[80 + tid] = v;
    }
    // product-vector inputs (small, all lanes): v = Rz(phi) Ry(theta) |0>
    const float4 e01 = *(const float4*)(inp);        // edges 0,1
    const float2 n0a = *(const float2*)(inp + 18);   // vert[1] (wire 9)
    const float2 n1a = *(const float2*)(inp + 20);   // vert[2] (wire 10)
    __syncwarp();

    // ---- lanes 0..9: build one matrix each through the single fused path
    if (tid < 10){
        M2 M = m_fused(shf[80 + g_i0[tid]],
                       shf[80 + g_i1[tid]],
                       shf[80 + g_i2[tid]]);
        float4* p = (float4*)shf;
        p[tid*2]   = make_float4(M.m00.x, M.m00.y, M.m01.x, M.m01.y);
        p[tid*2+1] = make_float4(M.m10.x, M.m10.y, M.m11.x, M.m11.y);
    }

    auto mkvec = [](float th, float ph, C2* v){
        float ct, st, cp, sp;
        __sincosf(0.5f*th, &st, &ct);
        __sincosf(0.5f*ph, &sp, &cp);
        v[0] = { ct*cp, -ct*sp };
        v[1] = { st*cp,  st*sp };
    };
    C2 vE0[2], vN0[2], vE1[2], vN1[2];
    mkvec(e01.x, e01.y, vE0);
    mkvec(n0a.x, n0a.y, vN0);
    mkvec(e01.z, e01.w, vE1);
    mkvec(n1a.x, n1a.y, vN1);
    __syncwarp();

    // ---- load the 10 matrices (20 x LDS.128)
    auto ldm = [&](int t){
        float4 u = ((const float4*)shf)[t*2];
        float4 w = ((const float4*)shf)[t*2+1];
        M2 M; M.m00 = {u.x,u.y}; M.m01 = {u.z,u.w};
              M.m10 = {w.x,w.y}; M.m11 = {w.z,w.w};
        return M;
    };
    const M2 ci0 = ldm(0), ci1 = ldm(1), ci2 = ldm(2), ci3 = ldm(3);
    const M2 A0f = ldm(4), A1f = ldm(5), A2f = ldm(6);
    const M2 B0f = ldm(7), B1f = ldm(8), B2f = ldm(9);

    // ---- init: regs r=(Nb<<1)|A1; task t nonzero iff A1==t>>1 && A2==t&1
    const int tA1 = (task == 4) ? 0 : (task >> 1);
    const int tA2 = (task == 4) ? 0 : (task & 1);
    C2 a[4];
#pragma unroll
    for (int r = 0; r < 4; r++){
        const int Nb = r >> 1, A1 = r & 1;
        C2 prod = (task == 4) ? cmul(vE0[E], vN0[Nb])
                              : cmul(vE1[E], vN1[Nb]);
        a[r] = (A1 == tA1 && A2 == tA2) ? prod : C2{0.f, 0.f};
    }

    // =================== evolve (U) ===================
    // crx(Nb -> A1): Nb=1 regs, butterfly on A1 (reg bit0)
    bfly(a[2], a[3], ci0);
    // cry(E -> A1): E=1 lanes, both reg pairs
    if (E){ bfly(a[0], a[1], ci1); bfly(a[2], a[3], ci1); }
    // crz(Nb -> A2): diagonal on Nb=1 regs, by lane A2
    {
        C2 d = A2 ? ci2.m11 : ci2.m00;
        a[2] = cmul(a[2], d); a[3] = cmul(a[3], d);
    }
    // cry(E -> A2): cross stage on lane bit0, predicated on E
    {
        C2 p0 = shf2(a[0], 1), p1 = shf2(a[1], 1);
        C2 p2 = shf2(a[2], 1), p3 = shf2(a[3], 1);
        if (E){
            a[0] = capply(ci3, A2, a[0], p0);
            a[1] = capply(ci3, A2, a[1], p1);
            a[2] = capply(ci3, A2, a[2], p2);
            a[3] = capply(ci3, A2, a[3], p3);
        }
    }
    // strong0: A0f on E (lane bit1) — cross stage
    {
        C2 p0 = shf2(a[0], 2), p1 = shf2(a[1], 2);
        C2 p2 = shf2(a[2], 2), p3 = shf2(a[3], 2);
        a[0] = capply(A0f, E, a[0], p0);
        a[1] = capply(A0f, E, a[1], p1);
        a[2] = capply(A0f, E, a[2], p2);
        a[3] = capply(A0f, E, a[3], p3);
    }
    // A1f on Nb (reg bit1)
    bfly(a[0], a[2], A1f); bfly(a[1], a[3], A1f);
    // A2f on A1 (reg bit0)
    bfly(a[0], a[1], A2f); bfly(a[2], a[3], A2f);
    // cnot(E -> Nb): E=1 lanes flip Nb (predicated renames -> SELs)
    if (E){ cswap(a[0], a[2]); cswap(a[1], a[3]); }
    // cnot(Nb -> A1): Nb=1 regs flip A1 (free rename)
    cswap(a[2], a[3]);
    // cnot(A1 -> E): A1=1 regs swap across lane E
    a[1] = shf2(a[1], 2);
    a[3] = shf2(a[3], 2);
    // strong1: B0f on A1 (reg bit0)
    bfly(a[0], a[1], B0f); bfly(a[2], a[3], B0f);
    // B1f on Nb (reg bit1)
    bfly(a[0], a[2], B1f); bfly(a[1], a[3], B1f);
    // B2f on A2 (lane bit0) — cross stage
    {
        C2 p0 = shf2(a[0], 1), p1 = shf2(a[1], 1);
        C2 p2 = shf2(a[2], 1), p3 = shf2(a[3], 1);
        a[0] = capply(B2f, A2, a[0], p0);
        a[1] = capply(B2f, A2, a[1], p1);
        a[2] = capply(B2f, A2, a[2], p2);
        a[3] = capply(B2f, A2, a[3], p3);
    }
    // cnot(A1 -> Nb): A1=1 regs flip Nb (free rename)
    cswap(a[1], a[3]);
    // cnot(Nb -> A2): Nb=1 regs swap across lane A2
    a[2] = shf2(a[2], 1);
    a[3] = shf2(a[3], 1);
    // cnot(A2 -> A1): A2=1 lanes flip A1 (predicated renames -> SELs)
    if (A2){ cswap(a[0], a[1]); cswap(a[2], a[3]); }
    // ==================================================

    // writeout: s = E*8 + Nb*4 + A1*2 + A2
    if (tid < 20){
#pragma unroll
        for (int r = 0; r < 4; r++){
            const int Nb = r >> 1, A1 = r & 1;
            shc[task*16 + E*8 + Nb*4 + A1*2 + A2] = a[r];
        }
    }
    __syncwarp();

    // ---- combine: 64 terms (en 0..3, s 0..15), 2 per lane
    float val = 0.f;
#pragma unroll
    for (int k = 0; k < 2; k++){
        const int T  = tid + 32*k;
        const int en = T >> 4;
        const int s  = T & 15;
        C2 amp = {0.f, 0.f};
#pragma unroll
        for (int q = 0; q < 4; q++)
            amp = cmadd(shc[64 + en*4 + q], shc[q*16 + s], amp);
        float p = amp.x*amp.x + amp.y*amp.y;
        val += ((s >> 2) & 1) ? -p : p;
    }

#pragma unroll
    for (int off = 16; off > 0; off >>= 1)
        val += __shfl_xor_sync(FULLMASK, val, off);
    if (tid == 0) out[0] = val;
}

extern "C" void kernel_launch(void* const* d_in, const int* in_sizes, int n_in,
                              void* d_out, int out_size)
{
    const float* inputs_flat = (const float*)d_in[0];
    const float* inits       = (const float*)d_in[1];
    const float* strong0     = (const float*)d_in[2];
    const float* strong1     = (const float*)d_in[3];
    // d_in[4] (update_params) provably does not affect the measured value.
    QMessagePassing_44272522887312_kernel<<<1, 32>>>(
        inputs_flat, inits, strong0, strong1, (float*)d_out);
}